// round 9
// baseline (speedup 1.0000x reference)
#include <cuda_runtime.h>

#define NN 10000
#define EE 640000
#define FIN 128
#define NH 8
#define FOUT 16
#define NEG 0.2f
#define EPSF 1e-16f

#define GEMM_BLOCKS 313          // ceil(10000/32)
#define COUNT_BLOCKS ((EE + 255) / 256)

// ---------------- scratch (static device memory; zero-initialized at load) -----
__device__ float g_proj[NN * FIN];      // 5.12 MB
__device__ float g_ssrc[NN * NH];
__device__ float g_stgt[NN * NH];
__device__ int   g_count[NN];           // zeroed at end of k_agg
__device__ int   g_offs[NN + 1];
__device__ int   g_cursor[NN];
__device__ int   g_ssorted[EE];         // src id per CSR slot
__device__ unsigned g_maxsrc[NH];       // zeroed at end of k_agg
__device__ unsigned g_maxtgt[NH];
__device__ float g_C[NH];               // softmax shift constants

__device__ __forceinline__ unsigned f2u_ord(float f) {
    unsigned u = __float_as_uint(f);
    return (u & 0x80000000u) ? ~u : (u | 0x80000000u);
}
__device__ __forceinline__ float u2f_ord(unsigned u) {
    return __uint_as_float((u & 0x80000000u) ? (u ^ 0x80000000u) : ~u);
}

// ---------------- fused: proj+skip GEMM (+bias,+scores)  ||  edge counting -----
__global__ void __launch_bounds__(256) k_fused(
    const float* __restrict__ x, const float* __restrict__ Wp,
    const float* __restrict__ Ws, const float* __restrict__ bias,
    const float* __restrict__ sw_src, const float* __restrict__ sw_tgt,
    const int* __restrict__ edges, float* __restrict__ out)
{
    __shared__ float4 xs4[2][16][32];   // 16 KB
    int t = threadIdx.x;

    if (blockIdx.x >= GEMM_BLOCKS) {
        int e = (blockIdx.x - GEMM_BLOCKS) * 256 + t;
        if (e < EE) atomicAdd(&g_count[edges[EE + e]], 1);
        return;
    }

    int sb = t >> 7;                    // sub-block 0/1
    int tt = t & 127;
    int node0 = blockIdx.x * 32 + sb * 16;
    if (node0 >= NN) return;            // tail half-block

    const float4* xg = (const float4*)(x + node0 * FIN);
    for (int i = tt; i < 512; i += 128) xs4[sb][i >> 5][i & 31] = xg[i];
    __syncwarp();
    __syncthreads();

    float accP[16], accS[16];
#pragma unroll
    for (int n = 0; n < 16; n++) { accP[n] = 0.0f; accS[n] = 0.0f; }

    const float4* wp4 = (const float4*)(Wp + tt * FIN);
    const float4* ws4 = (const float4*)(Ws + tt * FIN);
#pragma unroll 8
    for (int k = 0; k < 32; k++) {
        float4 a = wp4[k];
        float4 b = ws4[k];
#pragma unroll
        for (int n = 0; n < 16; n++) {
            float4 xv = xs4[sb][n][k];
            accP[n] += a.x * xv.x + a.y * xv.y + a.z * xv.z + a.w * xv.w;
            accS[n] += b.x * xv.x + b.y * xv.y + b.z * xv.z + b.w * xv.w;
        }
    }
    float bv = bias[tt];
#pragma unroll
    for (int n = 0; n < 16; n++) {
        g_proj[(node0 + n) * FIN + tt] = accP[n];
        out[(node0 + n) * FIN + tt] = accS[n] + bv;   // skip + bias baseline
    }

    // ---- epilogue: per-(node,head) scores via 16-lane shuffle reduction ----
    float swv = sw_src[tt], twv = sw_tgt[tt];
    int h = tt >> 4;
    bool leader = (tt & 15) == 0;
    float msrc = -3.4e38f, mtgt = -3.4e38f;
#pragma unroll
    for (int n = 0; n < 16; n++) {
        float ps = accP[n] * swv;
        float pt = accP[n] * twv;
#pragma unroll
        for (int o = 8; o; o >>= 1) {
            ps += __shfl_down_sync(0xffffffffu, ps, o, 16);
            pt += __shfl_down_sync(0xffffffffu, pt, o, 16);
        }
        if (leader) {
            g_ssrc[(node0 + n) * NH + h] = ps;
            g_stgt[(node0 + n) * NH + h] = pt;
            msrc = fmaxf(msrc, ps);
            mtgt = fmaxf(mtgt, pt);
        }
    }
    if (leader) {
        atomicMax(&g_maxsrc[h], f2u_ord(msrc));
        atomicMax(&g_maxtgt[h], f2u_ord(mtgt));
    }
}

// ---------------- CSR scan: coalesced smem staging + warp-shuffle scan ---------
__global__ void __launch_bounds__(1024) k_scan() {
    const int PER = 10;                 // 1024 * 10 >= NN
    __shared__ int cs[NN];              // 40 KB, coalesced staging
    __shared__ int wt[32];
    int t = threadIdx.x;

    for (int i = t; i < NN; i += 1024) cs[i] = g_count[i];   // coalesced, MLP=10
    __syncthreads();

    int base = t * PER;
    int loc[PER];
    int sum = 0;
#pragma unroll
    for (int i = 0; i < PER; i++) {
        int idx = base + i;
        int v = (idx < NN) ? cs[idx] : 0;
        loc[i] = sum;
        sum += v;
    }
    int lane = t & 31, w = t >> 5;
    int s = sum;
#pragma unroll
    for (int o = 1; o < 32; o <<= 1) {
        int y = __shfl_up_sync(0xffffffffu, s, o);
        if (lane >= o) s += y;
    }
    if (lane == 31) wt[w] = s;
    __syncthreads();
    if (w == 0) {
        int v = wt[lane];
        int s2 = v;
#pragma unroll
        for (int o = 1; o < 32; o <<= 1) {
            int y = __shfl_up_sync(0xffffffffu, s2, o);
            if (lane >= o) s2 += y;
        }
        wt[lane] = s2 - v;
    }
    __syncthreads();
    int off = (s - sum) + wt[w];
#pragma unroll
    for (int i = 0; i < PER; i++) {
        int idx = base + i;
        if (idx < NN) cs[idx] = off + loc[i];
    }
    __syncthreads();
    for (int i = t; i < NN; i += 1024) {   // coalesced write-out
        int o = cs[i];
        g_offs[i] = o;
        g_cursor[i] = o;
    }
    if (t == 1023) g_offs[NN] = off + sum;

    // softmax shift constants (upper bound of edge max; shift-invariant)
    if (t < NH) {
        float c = u2f_ord(g_maxsrc[t]) + u2f_ord(g_maxtgt[t]);
        g_C[t] = fmaxf(c, NEG * c);
    }
}

// ---------------- CSR scatter: src ids into segment order ----------------
__global__ void k_scatter(const int* __restrict__ edges) {
    int e = blockIdx.x * 256 + threadIdx.x;
    if (e < EE) {
        int p = atomicAdd(&g_cursor[edges[EE + e]], 1);
        g_ssorted[p] = edges[e];
    }
}

// ---------------- aggregation: block per node, barrier-free tiles --------------
// Each warp holds the tile's 32 src ids in lane regs (one coalesced LDG, x4
// redundant, L1-hit). Per group of 4 edges: lane l computes exp for edge l>>3,
// head l&7 (8 MUFU/edge, minimal); att + src reach consumer lanes via shfl.
// Lane l owns features [4l,4l+4) -> one LDG.128 covers a full 512B proj row.
// Tail guards (es < m) are warp-uniform: no divergence, no barriers in the loop.
__global__ void __launch_bounds__(128) k_agg(float* __restrict__ out) {
    __shared__ float4 red_s[4][32];
    __shared__ float  den_red[128];

    int n = blockIdx.x, t = threadIdx.x;
    int lane = t & 31, w = t >> 5;
    int hl = lane & 7;                           // head for exp work
    int h4 = lane >> 2;                          // head for feature work

    float stgt_l = g_stgt[n * NH + hl];
    float C_l = g_C[hl];

    if (t == 0) g_count[n] = 0;                  // re-zero for next replay
    if (n == 0 && t >= 16 && t < 24) g_maxsrc[t - 16] = 0u;
    if (n == 0 && t >= 24 && t < 32) g_maxtgt[t - 24] = 0u;

    int start = g_offs[n], end = g_offs[n + 1];
    float4 acc = make_float4(0.f, 0.f, 0.f, 0.f);
    float den_part = 0.f;

    for (int base = start; base < end; base += 32) {
        int m = end - base;                      // valid slots: lane < m (cap 32)
        int sid = (lane < m) ? g_ssorted[base + lane] : 0;
#pragma unroll
        for (int g2 = 0; g2 < 2; g2++) {
            int myslot = w + 16 * g2 + 4 * (lane >> 3);
            int esrc = __shfl_sync(0xffffffffu, sid, myslot);
            float ex = 0.f;
            if (myslot < m) {
                float v = g_ssrc[esrc * NH + hl] + stgt_l;
                ex = __expf(fmaxf(v, NEG * v) - C_l);
            }
            den_part += ex;
#pragma unroll
            for (int gi = 0; gi < 4; gi++) {
                int es = w + 16 * g2 + 4 * gi;   // warp-uniform
                if (es < m) {
                    float a = __shfl_sync(0xffffffffu, ex, (gi << 3) + h4);
                    int sv = __shfl_sync(0xffffffffu, sid, es);
                    float4 p = ((const float4*)(g_proj + sv * FIN))[lane];
                    acc.x += a * p.x; acc.y += a * p.y;
                    acc.z += a * p.z; acc.w += a * p.w;
                }
            }
        }
    }

    red_s[w][lane] = acc;
    den_red[t] = den_part;
    __syncthreads();
    if (w == 0) {
        float4 a = red_s[0][lane];
#pragma unroll
        for (int ww = 1; ww < 4; ww++) {
            float4 b = red_s[ww][lane];
            a.x += b.x; a.y += b.y; a.z += b.z; a.w += b.w;
        }
        float den = 0.f;
#pragma unroll
        for (int k = 0; k < 16; k++) den += den_red[h4 + k * 8];
        float inv = 1.0f / (den + EPSF);
        float4* o4 = (float4*)(out + n * FIN);
        float4 o = o4[lane];
        o.x += a.x * inv; o.y += a.y * inv; o.z += a.z * inv; o.w += a.w * inv;
        o4[lane] = o;
    }
}

// ---------------- launch ----------------
extern "C" void kernel_launch(void* const* d_in, const int* in_sizes, int n_in,
                              void* d_out, int out_size)
{
    const float* x     = (const float*)d_in[0];
    const int*   edges = (const int*)d_in[1];     // int32 (JAX x64 disabled)
    const float* Wp    = (const float*)d_in[2];
    const float* Ws    = (const float*)d_in[3];
    const float* s_src = (const float*)d_in[4];
    const float* s_tgt = (const float*)d_in[5];
    const float* bias  = (const float*)d_in[6];
    float* out = (float*)d_out;

    k_fused<<<GEMM_BLOCKS + COUNT_BLOCKS, 256>>>(x, Wp, Ws, bias, s_src, s_tgt, edges, out);
    k_scan<<<1, 1024>>>();
    k_scatter<<<(EE + 255) / 256, 256>>>(edges);
    k_agg<<<NN, 128>>>(out);
}

// round 10
// speedup vs baseline: 1.0206x; 1.0206x over previous
#include <cuda_runtime.h>

#define NN 10000
#define EE 640000
#define FIN 128
#define NH 8
#define FOUT 16
#define NEG 0.2f
#define EPSF 1e-16f

#define GEMM_BLOCKS 313          // ceil(10000/32)
#define COUNT_BLOCKS ((EE + 255) / 256)

// ---------------- scratch (static device memory; zero-initialized at load) -----
__device__ float g_proj[NN * FIN];      // 5.12 MB
__device__ float g_ssrc[NN * NH];
__device__ float g_stgt[NN * NH];
__device__ int   g_count[NN];           // zeroed at end of k_agg
__device__ int   g_offs[NN + 1];
__device__ int   g_cursor[NN];
__device__ int   g_ssorted[EE];         // src id per CSR slot
__device__ unsigned g_maxsrc[NH];       // zeroed at end of k_agg
__device__ unsigned g_maxtgt[NH];
__device__ float g_C[NH];               // softmax shift constants

__device__ __forceinline__ unsigned f2u_ord(float f) {
    unsigned u = __float_as_uint(f);
    return (u & 0x80000000u) ? ~u : (u | 0x80000000u);
}
__device__ __forceinline__ float u2f_ord(unsigned u) {
    return __uint_as_float((u & 0x80000000u) ? (u ^ 0x80000000u) : ~u);
}

// ---------------- fused: proj+skip GEMM (+bias,+scores)  ||  edge counting -----
__global__ void __launch_bounds__(256) k_fused(
    const float* __restrict__ x, const float* __restrict__ Wp,
    const float* __restrict__ Ws, const float* __restrict__ bias,
    const float* __restrict__ sw_src, const float* __restrict__ sw_tgt,
    const int* __restrict__ edges, float* __restrict__ out)
{
    __shared__ float4 xs4[2][16][32];   // 16 KB
    int t = threadIdx.x;

    if (blockIdx.x >= GEMM_BLOCKS) {
        int e = (blockIdx.x - GEMM_BLOCKS) * 256 + t;
        if (e < EE) atomicAdd(&g_count[edges[EE + e]], 1);
        return;
    }

    int sb = t >> 7;                    // sub-block 0/1
    int tt = t & 127;
    int node0 = blockIdx.x * 32 + sb * 16;
    if (node0 >= NN) return;            // tail half-block

    const float4* xg = (const float4*)(x + node0 * FIN);
    for (int i = tt; i < 512; i += 128) xs4[sb][i >> 5][i & 31] = xg[i];
    __syncwarp();
    __syncthreads();

    float accP[16], accS[16];
#pragma unroll
    for (int n = 0; n < 16; n++) { accP[n] = 0.0f; accS[n] = 0.0f; }

    const float4* wp4 = (const float4*)(Wp + tt * FIN);
    const float4* ws4 = (const float4*)(Ws + tt * FIN);
#pragma unroll 8
    for (int k = 0; k < 32; k++) {
        float4 a = wp4[k];
        float4 b = ws4[k];
#pragma unroll
        for (int n = 0; n < 16; n++) {
            float4 xv = xs4[sb][n][k];
            accP[n] += a.x * xv.x + a.y * xv.y + a.z * xv.z + a.w * xv.w;
            accS[n] += b.x * xv.x + b.y * xv.y + b.z * xv.z + b.w * xv.w;
        }
    }
    float bv = bias[tt];
#pragma unroll
    for (int n = 0; n < 16; n++) {
        g_proj[(node0 + n) * FIN + tt] = accP[n];
        out[(node0 + n) * FIN + tt] = accS[n] + bv;   // skip + bias baseline
    }

    // ---- epilogue: per-(node,head) scores via 16-lane shuffle reduction ----
    float swv = sw_src[tt], twv = sw_tgt[tt];
    int h = tt >> 4;
    bool leader = (tt & 15) == 0;
    float msrc = -3.4e38f, mtgt = -3.4e38f;
#pragma unroll
    for (int n = 0; n < 16; n++) {
        float ps = accP[n] * swv;
        float pt = accP[n] * twv;
#pragma unroll
        for (int o = 8; o; o >>= 1) {
            ps += __shfl_down_sync(0xffffffffu, ps, o, 16);
            pt += __shfl_down_sync(0xffffffffu, pt, o, 16);
        }
        if (leader) {
            g_ssrc[(node0 + n) * NH + h] = ps;
            g_stgt[(node0 + n) * NH + h] = pt;
            msrc = fmaxf(msrc, ps);
            mtgt = fmaxf(mtgt, pt);
        }
    }
    if (leader) {
        atomicMax(&g_maxsrc[h], f2u_ord(msrc));
        atomicMax(&g_maxtgt[h], f2u_ord(mtgt));
    }
}

// ---------------- CSR scan: coalesced smem staging + warp-shuffle scan ---------
__global__ void __launch_bounds__(1024) k_scan() {
    const int PER = 10;                 // 1024 * 10 >= NN
    __shared__ int cs[NN];              // 40 KB, coalesced staging
    __shared__ int wt[32];
    int t = threadIdx.x;

    for (int i = t; i < NN; i += 1024) cs[i] = g_count[i];   // coalesced, MLP=10
    __syncthreads();

    int base = t * PER;
    int loc[PER];
    int sum = 0;
#pragma unroll
    for (int i = 0; i < PER; i++) {
        int idx = base + i;
        int v = (idx < NN) ? cs[idx] : 0;
        loc[i] = sum;
        sum += v;
    }
    int lane = t & 31, w = t >> 5;
    int s = sum;
#pragma unroll
    for (int o = 1; o < 32; o <<= 1) {
        int y = __shfl_up_sync(0xffffffffu, s, o);
        if (lane >= o) s += y;
    }
    if (lane == 31) wt[w] = s;
    __syncthreads();
    if (w == 0) {
        int v = wt[lane];
        int s2 = v;
#pragma unroll
        for (int o = 1; o < 32; o <<= 1) {
            int y = __shfl_up_sync(0xffffffffu, s2, o);
            if (lane >= o) s2 += y;
        }
        wt[lane] = s2 - v;
    }
    __syncthreads();
    int off = (s - sum) + wt[w];
#pragma unroll
    for (int i = 0; i < PER; i++) {
        int idx = base + i;
        if (idx < NN) cs[idx] = off + loc[i];
    }
    __syncthreads();
    for (int i = t; i < NN; i += 1024) {   // coalesced write-out
        int o = cs[i];
        g_offs[i] = o;
        g_cursor[i] = o;
    }
    if (t == 1023) g_offs[NN] = off + sum;

    // softmax shift constants (upper bound of edge max; shift-invariant)
    if (t < NH) {
        float c = u2f_ord(g_maxsrc[t]) + u2f_ord(g_maxtgt[t]);
        g_C[t] = fmaxf(c, NEG * c);
    }
}

// ---------------- CSR scatter: src ids into segment order ----------------
__global__ void k_scatter(const int* __restrict__ edges) {
    int e = blockIdx.x * 256 + threadIdx.x;
    if (e < EE) {
        int p = atomicAdd(&g_cursor[edges[EE + e]], 1);
        g_ssorted[p] = edges[e];
    }
}

// ---------------- aggregation: block per node, inline softmax ------------------
// Tile = 32 edges. Staging (128 threads, 2 rounds): exp for (slot, head) with
// zero-padding for slot >= m; att stored head-major with pad-36 rows
// (bank = 4h+slot -> conflict-free; 144B rows keep LDS.128 alignment);
// src offsets premultiplied (sid*32 = float4-row) stored as int4-loadable ints.
// Compute: warp w owns contiguous slots [8w, 8w+8): 2 LDS.128 (att) +
// 2 LDS.128 (offs) + 8 LDG.128 + 32 FFMA, zero branches, MLP=8.
__global__ void __launch_bounds__(128, 8) k_agg(float* __restrict__ out) {
    __shared__ float  att_s[NH * 36];            // head-major, pad 36
    __shared__ int    offs_s[32];                // premultiplied float4 offsets
    __shared__ float4 red_s[4][32];
    __shared__ float  den_red[128];

    int n = blockIdx.x, t = threadIdx.x;
    int lane = t & 31, w = t >> 5;
    int hs = t & 7;                              // staging head
    int h4 = lane >> 2;                          // compute head

    float stgt_h = g_stgt[n * NH + hs];
    float C_h = g_C[hs];

    if (t == 0) g_count[n] = 0;                  // re-zero for next replay
    if (n == 0 && t >= 16 && t < 24) g_maxsrc[t - 16] = 0u;
    if (n == 0 && t >= 24 && t < 32) g_maxtgt[t - 24] = 0u;

    int start = g_offs[n], end = g_offs[n + 1];
    float4 acc = make_float4(0.f, 0.f, 0.f, 0.f);
    float den_part = 0.f;
    const float4* P4 = (const float4*)g_proj;

    for (int base = start; base < end; base += 32) {
        int m = min(32, end - base);
        __syncthreads();                         // protect smem from prev tile
#pragma unroll
        for (int r = 0; r < 2; r++) {
            int slot = (t >> 3) + r * 16;
            int sid = 0;
            float ex = 0.f;
            if (slot < m) {
                sid = g_ssorted[base + slot];
                float v = g_ssrc[sid * NH + hs] + stgt_h;
                ex = __expf(fmaxf(v, NEG * v) - C_h);
            }
            att_s[hs * 36 + slot] = ex;
            den_part += ex;
            if (hs == 0) offs_s[slot] = sid * 32;   // float4-row offset (pad->0)
        }
        __syncthreads();

        int jb = w * 8;
        float4 aA = *(const float4*)&att_s[h4 * 36 + jb];
        float4 aB = *(const float4*)&att_s[h4 * 36 + jb + 4];
        int4 oA = *(const int4*)&offs_s[jb];
        int4 oB = *(const int4*)&offs_s[jb + 4];
        float4 p0 = P4[oA.x + lane];
        float4 p1 = P4[oA.y + lane];
        float4 p2 = P4[oA.z + lane];
        float4 p3 = P4[oA.w + lane];
        float4 p4 = P4[oB.x + lane];
        float4 p5 = P4[oB.y + lane];
        float4 p6 = P4[oB.z + lane];
        float4 p7 = P4[oB.w + lane];
        acc.x += aA.x * p0.x; acc.y += aA.x * p0.y; acc.z += aA.x * p0.z; acc.w += aA.x * p0.w;
        acc.x += aA.y * p1.x; acc.y += aA.y * p1.y; acc.z += aA.y * p1.z; acc.w += aA.y * p1.w;
        acc.x += aA.z * p2.x; acc.y += aA.z * p2.y; acc.z += aA.z * p2.z; acc.w += aA.z * p2.w;
        acc.x += aA.w * p3.x; acc.y += aA.w * p3.y; acc.z += aA.w * p3.z; acc.w += aA.w * p3.w;
        acc.x += aB.x * p4.x; acc.y += aB.x * p4.y; acc.z += aB.x * p4.z; acc.w += aB.x * p4.w;
        acc.x += aB.y * p5.x; acc.y += aB.y * p5.y; acc.z += aB.y * p5.z; acc.w += aB.y * p5.w;
        acc.x += aB.z * p6.x; acc.y += aB.z * p6.y; acc.z += aB.z * p6.z; acc.w += aB.z * p6.w;
        acc.x += aB.w * p7.x; acc.y += aB.w * p7.y; acc.z += aB.w * p7.z; acc.w += aB.w * p7.w;
    }

    red_s[w][lane] = acc;
    den_red[t] = den_part;
    __syncthreads();
    if (w == 0) {
        float4 a = red_s[0][lane];
#pragma unroll
        for (int ww = 1; ww < 4; ww++) {
            float4 b = red_s[ww][lane];
            a.x += b.x; a.y += b.y; a.z += b.z; a.w += b.w;
        }
        float den = 0.f;
#pragma unroll
        for (int k = 0; k < 16; k++) den += den_red[h4 + k * 8];
        float inv = 1.0f / (den + EPSF);
        float4* o4 = (float4*)(out + n * FIN);
        float4 o = o4[lane];
        o.x += a.x * inv; o.y += a.y * inv; o.z += a.z * inv; o.w += a.w * inv;
        o4[lane] = o;
    }
}

// ---------------- launch ----------------
extern "C" void kernel_launch(void* const* d_in, const int* in_sizes, int n_in,
                              void* d_out, int out_size)
{
    const float* x     = (const float*)d_in[0];
    const int*   edges = (const int*)d_in[1];     // int32 (JAX x64 disabled)
    const float* Wp    = (const float*)d_in[2];
    const float* Ws    = (const float*)d_in[3];
    const float* s_src = (const float*)d_in[4];
    const float* s_tgt = (const float*)d_in[5];
    const float* bias  = (const float*)d_in[6];
    float* out = (float*)d_out;

    k_fused<<<GEMM_BLOCKS + COUNT_BLOCKS, 256>>>(x, Wp, Ws, bias, s_src, s_tgt, edges, out);
    k_scan<<<1, 1024>>>();
    k_scatter<<<(EE + 255) / 256, 256>>>(edges);
    k_agg<<<NN, 128>>>(out);
}

// round 12
// speedup vs baseline: 1.1101x; 1.0877x over previous
#include <cuda_runtime.h>
#include <cuda_fp16.h>

#define NN 10000
#define EE 640000
#define FIN 128
#define NH 8
#define FOUT 16
#define NEG 0.2f
#define EPSF 1e-16f

#define GEMM_BLOCKS 313          // ceil(10000/32)
#define COUNT_BLOCKS ((EE + 255) / 256)

// ---------------- scratch (static device memory; zero-initialized at load) -----
__device__ __half g_proj16[NN * FIN];   // 2.56 MB, fp16 proj for aggregation
__device__ float g_ssrc[NN * NH];
__device__ float g_stgt[NN * NH];
__device__ int   g_count[NN];           // zeroed at end of k_agg
__device__ int   g_offs[NN + 1];
__device__ int   g_cursor[NN];
__device__ int   g_ssorted[EE];         // src id per CSR slot
__device__ unsigned g_maxsrc[NH];       // zeroed at end of k_agg
__device__ unsigned g_maxtgt[NH];
__device__ float g_C[NH];               // softmax shift constants

__device__ __forceinline__ unsigned f2u_ord(float f) {
    unsigned u = __float_as_uint(f);
    return (u & 0x80000000u) ? ~u : (u | 0x80000000u);
}
__device__ __forceinline__ float u2f_ord(unsigned u) {
    return __uint_as_float((u & 0x80000000u) ? (u ^ 0x80000000u) : ~u);
}

// ---------------- fused: proj+skip GEMM (+bias,+scores)  ||  edge counting -----
__global__ void __launch_bounds__(256) k_fused(
    const float* __restrict__ x, const float* __restrict__ Wp,
    const float* __restrict__ Ws, const float* __restrict__ bias,
    const float* __restrict__ sw_src, const float* __restrict__ sw_tgt,
    const int* __restrict__ edges, float* __restrict__ out)
{
    __shared__ float4 xs4[2][16][32];   // 16 KB
    int t = threadIdx.x;

    if (blockIdx.x >= GEMM_BLOCKS) {
        int e = (blockIdx.x - GEMM_BLOCKS) * 256 + t;
        if (e < EE) atomicAdd(&g_count[edges[EE + e]], 1);
        return;
    }

    int sb = t >> 7;                    // sub-block 0/1
    int tt = t & 127;
    int node0 = blockIdx.x * 32 + sb * 16;
    if (node0 >= NN) return;            // tail half-block

    const float4* xg = (const float4*)(x + node0 * FIN);
    for (int i = tt; i < 512; i += 128) xs4[sb][i >> 5][i & 31] = xg[i];
    __syncwarp();
    __syncthreads();

    float accP[16], accS[16];
#pragma unroll
    for (int n = 0; n < 16; n++) { accP[n] = 0.0f; accS[n] = 0.0f; }

    const float4* wp4 = (const float4*)(Wp + tt * FIN);
    const float4* ws4 = (const float4*)(Ws + tt * FIN);
#pragma unroll 8
    for (int k = 0; k < 32; k++) {
        float4 a = wp4[k];
        float4 b = ws4[k];
#pragma unroll
        for (int n = 0; n < 16; n++) {
            float4 xv = xs4[sb][n][k];
            accP[n] += a.x * xv.x + a.y * xv.y + a.z * xv.z + a.w * xv.w;
            accS[n] += b.x * xv.x + b.y * xv.y + b.z * xv.z + b.w * xv.w;
        }
    }
    float bv = bias[tt];
#pragma unroll
    for (int n = 0; n < 16; n++) {
        g_proj16[(node0 + n) * FIN + tt] = __float2half(accP[n]);
        out[(node0 + n) * FIN + tt] = accS[n] + bv;   // skip + bias baseline
    }

    // ---- epilogue: per-(node,head) scores via 16-lane shuffle reduction ----
    float swv = sw_src[tt], twv = sw_tgt[tt];
    int h = tt >> 4;
    bool leader = (tt & 15) == 0;
    float msrc = -3.4e38f, mtgt = -3.4e38f;
#pragma unroll
    for (int n = 0; n < 16; n++) {
        float ps = accP[n] * swv;
        float pt = accP[n] * twv;
#pragma unroll
        for (int o = 8; o; o >>= 1) {
            ps += __shfl_down_sync(0xffffffffu, ps, o, 16);
            pt += __shfl_down_sync(0xffffffffu, pt, o, 16);
        }
        if (leader) {
            g_ssrc[(node0 + n) * NH + h] = ps;
            g_stgt[(node0 + n) * NH + h] = pt;
            msrc = fmaxf(msrc, ps);
            mtgt = fmaxf(mtgt, pt);
        }
    }
    if (leader) {
        atomicMax(&g_maxsrc[h], f2u_ord(msrc));
        atomicMax(&g_maxtgt[h], f2u_ord(mtgt));
    }
}

// ---------------- CSR scan: coalesced smem staging + warp-shuffle scan ---------
__global__ void __launch_bounds__(1024) k_scan() {
    const int PER = 10;                 // 1024 * 10 >= NN
    __shared__ int cs[NN];              // 40 KB, coalesced staging
    __shared__ int wt[32];
    int t = threadIdx.x;

    for (int i = t; i < NN; i += 1024) cs[i] = g_count[i];   // coalesced, MLP=10
    __syncthreads();

    int base = t * PER;
    int loc[PER];
    int sum = 0;
#pragma unroll
    for (int i = 0; i < PER; i++) {
        int idx = base + i;
        int v = (idx < NN) ? cs[idx] : 0;
        loc[i] = sum;
        sum += v;
    }
    int lane = t & 31, w = t >> 5;
    int s = sum;
#pragma unroll
    for (int o = 1; o < 32; o <<= 1) {
        int y = __shfl_up_sync(0xffffffffu, s, o);
        if (lane >= o) s += y;
    }
    if (lane == 31) wt[w] = s;
    __syncthreads();
    if (w == 0) {
        int v = wt[lane];
        int s2 = v;
#pragma unroll
        for (int o = 1; o < 32; o <<= 1) {
            int y = __shfl_up_sync(0xffffffffu, s2, o);
            if (lane >= o) s2 += y;
        }
        wt[lane] = s2 - v;
    }
    __syncthreads();
    int off = (s - sum) + wt[w];
#pragma unroll
    for (int i = 0; i < PER; i++) {
        int idx = base + i;
        if (idx < NN) cs[idx] = off + loc[i];
    }
    __syncthreads();
    for (int i = t; i < NN; i += 1024) {   // coalesced write-out
        int o = cs[i];
        g_offs[i] = o;
        g_cursor[i] = o;
    }
    if (t == 1023) g_offs[NN] = off + sum;

    // softmax shift constants (upper bound of edge max; shift-invariant)
    if (t < NH) {
        float c = u2f_ord(g_maxsrc[t]) + u2f_ord(g_maxtgt[t]);
        g_C[t] = fmaxf(c, NEG * c);
    }
}

// ---------------- CSR scatter: src ids into segment order ----------------
__global__ void k_scatter(const int* __restrict__ edges) {
    int e = blockIdx.x * 256 + threadIdx.x;
    if (e < EE) {
        int p = atomicAdd(&g_cursor[edges[EE + e]], 1);
        g_ssorted[p] = edges[e];
    }
}

// ---------------- aggregation: block per node, inline softmax, fp16 gather -----
// R8 structure (regs ~32, occ ~85%): smem staging of exp + src per 32-edge tile
// (2 barriers/tile), warp w handles edges w, w+4, ...; lane l owns features
// [4l,4l+4) = 4 halves = one LDG.64 per edge (half the L2 traffic of fp32).
__global__ void __launch_bounds__(128) k_agg(float* __restrict__ out) {
    __shared__ int    src_s[32];
    __shared__ float  att_s[32][NH];
    __shared__ float4 red_s[4][32];
    __shared__ float  den_red[128];
    __shared__ float  stgt_s[NH], C_s[NH];

    int n = blockIdx.x, t = threadIdx.x;
    int lane = t & 31, w = t >> 5;

    if (t < NH) { stgt_s[t] = g_stgt[n * NH + t]; C_s[t] = g_C[t]; }
    if (t == 8) g_count[n] = 0;                  // re-zero for next replay
    if (n == 0 && t >= 16 && t < 24) g_maxsrc[t - 16] = 0u;
    if (n == 0 && t >= 24 && t < 32) g_maxtgt[t - 24] = 0u;
    __syncthreads();

    int start = g_offs[n], end = g_offs[n + 1];
    int hs = t & 7;                              // staging head
    float stgt_h = stgt_s[hs];
    float C_h = C_s[hs];
    float4 acc = make_float4(0.f, 0.f, 0.f, 0.f);
    float den_part = 0.f;
    int h4 = lane >> 2;                          // compute head (per feature group)

    for (int base = start; base < end; base += 32) {
        int m = min(32, end - base);
        __syncthreads();
        if (t < m) src_s[t] = g_ssorted[base + t];
        __syncthreads();
#pragma unroll
        for (int j = 0; j < 2; j++) {
            int slot = (t + j * 128) >> 3;
            if (slot < m) {
                float v = g_ssrc[src_s[slot] * NH + hs] + stgt_h;
                float ex = __expf(fmaxf(v, NEG * v) - C_h);
                att_s[slot][hs] = ex;
                den_part += ex;
            }
        }
        __syncthreads();
        int j = w;
        for (; j + 12 < m; j += 16) {            // 4 edges/iter -> MLP=4
            float a0 = att_s[j +  0][h4];
            float a1 = att_s[j +  4][h4];
            float a2 = att_s[j +  8][h4];
            float a3 = att_s[j + 12][h4];
            float2 r0 = ((const float2*)(g_proj16 + src_s[j +  0] * FIN))[lane];
            float2 r1 = ((const float2*)(g_proj16 + src_s[j +  4] * FIN))[lane];
            float2 r2 = ((const float2*)(g_proj16 + src_s[j +  8] * FIN))[lane];
            float2 r3 = ((const float2*)(g_proj16 + src_s[j + 12] * FIN))[lane];
            float2 f0a = __half22float2(*(__half2*)&r0.x), f0b = __half22float2(*(__half2*)&r0.y);
            float2 f1a = __half22float2(*(__half2*)&r1.x), f1b = __half22float2(*(__half2*)&r1.y);
            float2 f2a = __half22float2(*(__half2*)&r2.x), f2b = __half22float2(*(__half2*)&r2.y);
            float2 f3a = __half22float2(*(__half2*)&r3.x), f3b = __half22float2(*(__half2*)&r3.y);
            acc.x += a0 * f0a.x; acc.y += a0 * f0a.y; acc.z += a0 * f0b.x; acc.w += a0 * f0b.y;
            acc.x += a1 * f1a.x; acc.y += a1 * f1a.y; acc.z += a1 * f1b.x; acc.w += a1 * f1b.y;
            acc.x += a2 * f2a.x; acc.y += a2 * f2a.y; acc.z += a2 * f2b.x; acc.w += a2 * f2b.y;
            acc.x += a3 * f3a.x; acc.y += a3 * f3a.y; acc.z += a3 * f3b.x; acc.w += a3 * f3b.y;
        }
        for (; j < m; j += 4) {
            float a = att_s[j][h4];
            float2 r = ((const float2*)(g_proj16 + src_s[j] * FIN))[lane];
            float2 fa = __half22float2(*(__half2*)&r.x), fb = __half22float2(*(__half2*)&r.y);
            acc.x += a * fa.x; acc.y += a * fa.y; acc.z += a * fb.x; acc.w += a * fb.y;
        }
    }

    red_s[w][lane] = acc;
    den_red[t] = den_part;
    __syncthreads();
    if (w == 0) {
        float4 a = red_s[0][lane];
#pragma unroll
        for (int ww = 1; ww < 4; ww++) {
            float4 b = red_s[ww][lane];
            a.x += b.x; a.y += b.y; a.z += b.z; a.w += b.w;
        }
        float den = 0.f;
#pragma unroll
        for (int k = 0; k < 16; k++) den += den_red[h4 + k * 8];
        float inv = 1.0f / (den + EPSF);
        float4* o4 = (float4*)(out + n * FIN);
        float4 o = o4[lane];
        o.x += a.x * inv; o.y += a.y * inv; o.z += a.z * inv; o.w += a.w * inv;
        o4[lane] = o;
    }
}

// ---------------- launch ----------------
extern "C" void kernel_launch(void* const* d_in, const int* in_sizes, int n_in,
                              void* d_out, int out_size)
{
    const float* x     = (const float*)d_in[0];
    const int*   edges = (const int*)d_in[1];     // int32 (JAX x64 disabled)
    const float* Wp    = (const float*)d_in[2];
    const float* Ws    = (const float*)d_in[3];
    const float* s_src = (const float*)d_in[4];
    const float* s_tgt = (const float*)d_in[5];
    const float* bias  = (const float*)d_in[6];
    float* out = (float*)d_out;

    k_fused<<<GEMM_BLOCKS + COUNT_BLOCKS, 256>>>(x, Wp, Ws, bias, s_src, s_tgt, edges, out);
    k_scan<<<1, 1024>>>();
    k_scatter<<<(EE + 255) / 256, 256>>>(edges);
    k_agg<<<NN, 128>>>(out);
}

// round 14
// speedup vs baseline: 1.3137x; 1.1834x over previous
#include <cuda_runtime.h>
#include <cuda_fp16.h>

#define NN 10000
#define EE 640000
#define FIN 128
#define NH 8
#define FOUT 16
#define NEG 0.2f
#define EPSF 1e-16f

#define GEMM_BLOCKS 625          // 10000 / 16
#define COUNT_BLOCKS ((EE + 127) / 128)

// ---------------- scratch (static device memory; zero-initialized at load) -----
__device__ __half g_proj16[NN * FIN];   // 2.56 MB, fp16 proj for aggregation
__device__ float g_ssrc[NN * NH];
__device__ float g_stgt[NN * NH];
__device__ int   g_count[NN];           // zeroed at end of k_agg
__device__ int   g_offs[NN + 1];
__device__ int   g_cursor[NN];
__device__ int   g_ssorted[EE];         // src id per CSR slot
__device__ unsigned g_maxsrc[NH];       // zeroed at end of k_agg
__device__ unsigned g_maxtgt[NH];
__device__ float g_C[NH];               // softmax shift constants

__device__ __forceinline__ unsigned f2u_ord(float f) {
    unsigned u = __float_as_uint(f);
    return (u & 0x80000000u) ? ~u : (u | 0x80000000u);
}
__device__ __forceinline__ float u2f_ord(unsigned u) {
    return __uint_as_float((u & 0x80000000u) ? (u ^ 0x80000000u) : ~u);
}

// ---------------- fused: proj+skip GEMM (+bias,+scores)  ||  edge counting -----
// GEMM blocks: 128 threads, 16 nodes; thread t owns output col t of BOTH mats.
// W staged in fp16 smem, k-split in 2 halves of 64. Row pad to 68 halves
// (34 words ≡ 2 mod 32 -> LDS.64 conflict-free). Kills the 512B-stride LDG
// replay storm of the register-resident W version.
__global__ void __launch_bounds__(128) k_fused(
    const float* __restrict__ x, const float* __restrict__ Wp,
    const float* __restrict__ Ws, const float* __restrict__ bias,
    const float* __restrict__ sw_src, const float* __restrict__ sw_tgt,
    const int* __restrict__ edges, float* __restrict__ out)
{
    __shared__ float4 xs4[16][32];          // 8 KB
    __shared__ __half wsm[2][128][68];      // 34.8 KB
    int t = threadIdx.x;

    if (blockIdx.x >= GEMM_BLOCKS) {
        int e = (blockIdx.x - GEMM_BLOCKS) * 128 + t;
        if (e < EE) atomicAdd(&g_count[edges[EE + e]], 1);
        return;
    }

    int node0 = blockIdx.x * 16;

    const float4* xg = (const float4*)(x + node0 * FIN);
    for (int i = t; i < 512; i += 128) xs4[i >> 5][i & 31] = xg[i];

    float accP[16], accS[16];
#pragma unroll
    for (int n = 0; n < 16; n++) { accP[n] = 0.0f; accS[n] = 0.0f; }

    for (int kh = 0; kh < 2; kh++) {
        __syncthreads();                    // also orders x-tile on first pass
        // stage W[*, kh*64 .. +64) for both matrices, fp16, coalesced gmem reads
        for (int j = t; j < 2048; j += 128) {
            int col = j >> 4;               // 16 float4 per col
            int kk = (j & 15) << 2;         // half-index 0..60
            float4 wv = *(const float4*)(Wp + col * FIN + kh * 64 + kk);
            float4 sv = *(const float4*)(Ws + col * FIN + kh * 64 + kk);
            __half2* dp = (__half2*)&wsm[0][col][kk];
            dp[0] = __floats2half2_rn(wv.x, wv.y);
            dp[1] = __floats2half2_rn(wv.z, wv.w);
            __half2* ds = (__half2*)&wsm[1][col][kk];
            ds[0] = __floats2half2_rn(sv.x, sv.y);
            ds[1] = __floats2half2_rn(sv.z, sv.w);
        }
        __syncthreads();

#pragma unroll 4
        for (int k = 0; k < 16; k++) {
            uint2 ra = *(const uint2*)&wsm[0][t][k * 4];
            uint2 rb = *(const uint2*)&wsm[1][t][k * 4];
            float2 a01 = __half22float2(*(__half2*)&ra.x);
            float2 a23 = __half22float2(*(__half2*)&ra.y);
            float2 b01 = __half22float2(*(__half2*)&rb.x);
            float2 b23 = __half22float2(*(__half2*)&rb.y);
#pragma unroll
            for (int n = 0; n < 16; n++) {
                float4 xv = xs4[n][kh * 16 + k];
                accP[n] += a01.x * xv.x + a01.y * xv.y + a23.x * xv.z + a23.y * xv.w;
                accS[n] += b01.x * xv.x + b01.y * xv.y + b23.x * xv.z + b23.y * xv.w;
            }
        }
    }

    float bv = bias[t];
#pragma unroll
    for (int n = 0; n < 16; n++) {
        g_proj16[(node0 + n) * FIN + t] = __float2half(accP[n]);
        out[(node0 + n) * FIN + t] = accS[n] + bv;   // skip + bias baseline
    }

    // ---- epilogue: per-(node,head) scores via 16-lane shuffle reduction ----
    float swv = sw_src[t], twv = sw_tgt[t];
    int h = t >> 4;
    bool leader = (t & 15) == 0;
    float msrc = -3.4e38f, mtgt = -3.4e38f;
#pragma unroll
    for (int n = 0; n < 16; n++) {
        float ps = accP[n] * swv;
        float pt = accP[n] * twv;
#pragma unroll
        for (int o = 8; o; o >>= 1) {
            ps += __shfl_down_sync(0xffffffffu, ps, o, 16);
            pt += __shfl_down_sync(0xffffffffu, pt, o, 16);
        }
        if (leader) {
            g_ssrc[(node0 + n) * NH + h] = ps;
            g_stgt[(node0 + n) * NH + h] = pt;
            msrc = fmaxf(msrc, ps);
            mtgt = fmaxf(mtgt, pt);
        }
    }
    if (leader) {
        atomicMax(&g_maxsrc[h], f2u_ord(msrc));
        atomicMax(&g_maxtgt[h], f2u_ord(mtgt));
    }
}

// ---------------- CSR scan: coalesced smem staging + warp-shuffle scan ---------
__global__ void __launch_bounds__(1024) k_scan() {
    const int PER = 10;                 // 1024 * 10 >= NN
    __shared__ int cs[NN];              // 40 KB, coalesced staging
    __shared__ int wt[32];
    int t = threadIdx.x;

    for (int i = t; i < NN; i += 1024) cs[i] = g_count[i];   // coalesced, MLP=10
    __syncthreads();

    int base = t * PER;
    int loc[PER];
    int sum = 0;
#pragma unroll
    for (int i = 0; i < PER; i++) {
        int idx = base + i;
        int v = (idx < NN) ? cs[idx] : 0;
        loc[i] = sum;
        sum += v;
    }
    int lane = t & 31, w = t >> 5;
    int s = sum;
#pragma unroll
    for (int o = 1; o < 32; o <<= 1) {
        int y = __shfl_up_sync(0xffffffffu, s, o);
        if (lane >= o) s += y;
    }
    if (lane == 31) wt[w] = s;
    __syncthreads();
    if (w == 0) {
        int v = wt[lane];
        int s2 = v;
#pragma unroll
        for (int o = 1; o < 32; o <<= 1) {
            int y = __shfl_up_sync(0xffffffffu, s2, o);
            if (lane >= o) s2 += y;
        }
        wt[lane] = s2 - v;
    }
    __syncthreads();
    int off = (s - sum) + wt[w];
#pragma unroll
    for (int i = 0; i < PER; i++) {
        int idx = base + i;
        if (idx < NN) cs[idx] = off + loc[i];
    }
    __syncthreads();
    for (int i = t; i < NN; i += 1024) {   // coalesced write-out
        int o = cs[i];
        g_offs[i] = o;
        g_cursor[i] = o;
    }
    if (t == 1023) g_offs[NN] = off + sum;

    // softmax shift constants (upper bound of edge max; shift-invariant)
    if (t < NH) {
        float c = u2f_ord(g_maxsrc[t]) + u2f_ord(g_maxtgt[t]);
        g_C[t] = fmaxf(c, NEG * c);
    }
}

// ---------------- CSR scatter: src ids into segment order ----------------
__global__ void k_scatter(const int* __restrict__ edges) {
    int e = blockIdx.x * 256 + threadIdx.x;
    if (e < EE) {
        int p = atomicAdd(&g_cursor[edges[EE + e]], 1);
        g_ssorted[p] = edges[e];
    }
}

// ---------------- aggregation: block per node, inline softmax, fp16 gather -----
// R12 structure unchanged (regs ~32, occ ~85%).
__global__ void __launch_bounds__(128) k_agg(float* __restrict__ out) {
    __shared__ int    src_s[32];
    __shared__ float  att_s[32][NH];
    __shared__ float4 red_s[4][32];
    __shared__ float  den_red[128];
    __shared__ float  stgt_s[NH], C_s[NH];

    int n = blockIdx.x, t = threadIdx.x;
    int lane = t & 31, w = t >> 5;

    if (t < NH) { stgt_s[t] = g_stgt[n * NH + t]; C_s[t] = g_C[t]; }
    if (t == 8) g_count[n] = 0;                  // re-zero for next replay
    if (n == 0 && t >= 16 && t < 24) g_maxsrc[t - 16] = 0u;
    if (n == 0 && t >= 24 && t < 32) g_maxtgt[t - 24] = 0u;
    __syncthreads();

    int start = g_offs[n], end = g_offs[n + 1];
    int hs = t & 7;                              // staging head
    float stgt_h = stgt_s[hs];
    float C_h = C_s[hs];
    float4 acc = make_float4(0.f, 0.f, 0.f, 0.f);
    float den_part = 0.f;
    int h4 = lane >> 2;                          // compute head (per feature group)

    for (int base = start; base < end; base += 32) {
        int m = min(32, end - base);
        __syncthreads();
        if (t < m) src_s[t] = g_ssorted[base + t];
        __syncthreads();
#pragma unroll
        for (int j = 0; j < 2; j++) {
            int slot = (t + j * 128) >> 3;
            if (slot < m) {
                float v = g_ssrc[src_s[slot] * NH + hs] + stgt_h;
                float ex = __expf(fmaxf(v, NEG * v) - C_h);
                att_s[slot][hs] = ex;
                den_part += ex;
            }
        }
        __syncthreads();
        int j = w;
        for (; j + 12 < m; j += 16) {            // 4 edges/iter -> MLP=4
            float a0 = att_s[j +  0][h4];
            float a1 = att_s[j +  4][h4];
            float a2 = att_s[j +  8][h4];
            float a3 = att_s[j + 12][h4];
            float2 r0 = ((const float2*)(g_proj16 + src_s[j +  0] * FIN))[lane];
            float2 r1 = ((const float2*)(g_proj16 + src_s[j +  4] * FIN))[lane];
            float2 r2 = ((const float2*)(g_proj16 + src_s[j +  8] * FIN))[lane];
            float2 r3 = ((const float2*)(g_proj16 + src_s[j + 12] * FIN))[lane];
            float2 f0a = __half22float2(*(__half2*)&r0.x), f0b = __half22float2(*(__half2*)&r0.y);
            float2 f1a = __half22float2(*(__half2*)&r1.x), f1b = __half22float2(*(__half2*)&r1.y);
            float2 f2a = __half22float2(*(__half2*)&r2.x), f2b = __half22float2(*(__half2*)&r2.y);
            float2 f3a = __half22float2(*(__half2*)&r3.x), f3b = __half22float2(*(__half2*)&r3.y);
            acc.x += a0 * f0a.x; acc.y += a0 * f0a.y; acc.z += a0 * f0b.x; acc.w += a0 * f0b.y;
            acc.x += a1 * f1a.x; acc.y += a1 * f1a.y; acc.z += a1 * f1b.x; acc.w += a1 * f1b.y;
            acc.x += a2 * f2a.x; acc.y += a2 * f2a.y; acc.z += a2 * f2b.x; acc.w += a2 * f2b.y;
            acc.x += a3 * f3a.x; acc.y += a3 * f3a.y; acc.z += a3 * f3b.x; acc.w += a3 * f3b.y;
        }
        for (; j < m; j += 4) {
            float a = att_s[j][h4];
            float2 r = ((const float2*)(g_proj16 + src_s[j] * FIN))[lane];
            float2 fa = __half22float2(*(__half2*)&r.x), fb = __half22float2(*(__half2*)&r.y);
            acc.x += a * fa.x; acc.y += a * fa.y; acc.z += a * fb.x; acc.w += a * fb.y;
        }
    }

    red_s[w][lane] = acc;
    den_red[t] = den_part;
    __syncthreads();
    if (w == 0) {
        float4 a = red_s[0][lane];
#pragma unroll
        for (int ww = 1; ww < 4; ww++) {
            float4 b = red_s[ww][lane];
            a.x += b.x; a.y += b.y; a.z += b.z; a.w += b.w;
        }
        float den = 0.f;
#pragma unroll
        for (int k = 0; k < 16; k++) den += den_red[h4 + k * 8];
        float inv = 1.0f / (den + EPSF);
        float4* o4 = (float4*)(out + n * FIN);
        float4 o = o4[lane];
        o.x += a.x * inv; o.y += a.y * inv; o.z += a.z * inv; o.w += a.w * inv;
        o4[lane] = o;
    }
}

// ---------------- launch ----------------
extern "C" void kernel_launch(void* const* d_in, const int* in_sizes, int n_in,
                              void* d_out, int out_size)
{
    const float* x     = (const float*)d_in[0];
    const int*   edges = (const int*)d_in[1];     // int32 (JAX x64 disabled)
    const float* Wp    = (const float*)d_in[2];
    const float* Ws    = (const float*)d_in[3];
    const float* s_src = (const float*)d_in[4];
    const float* s_tgt = (const float*)d_in[5];
    const float* bias  = (const float*)d_in[6];
    float* out = (float*)d_out;

    k_fused<<<GEMM_BLOCKS + COUNT_BLOCKS, 128>>>(x, Wp, Ws, bias, s_src, s_tgt, edges, out);
    k_scan<<<1, 1024>>>();
    k_scatter<<<(EE + 255) / 256, 256>>>(edges);
    k_agg<<<NN, 128>>>(out);
}